// round 14
// baseline (speedup 1.0000x reference)
#include <cuda_runtime.h>
#include <cuda_bf16.h>
#include <cstdint>
#include <cstdio>

typedef __nv_bfloat16 bf16;

#define E_DIM 1024
#define H_NUM 16
#define D_DIM 64
#define L_SEQ 2048
#define B_NUM 4
#define ROWS 8192   /* B*L */
#define KW 17

// ---------------- scratch (static device allocations; no cudaMalloc) -------
__device__ bf16  g_xh[ROWS * E_DIM];
__device__ bf16  g_xl[ROWS * E_DIM];
__device__ bf16  g_wh[E_DIM * 2 * E_DIM];   /* Wkv split */
__device__ bf16  g_wl[E_DIM * 2 * E_DIM];
__device__ bf16  g_wqh[E_DIM * E_DIM];      /* Wq split; reused for Wout */
__device__ bf16  g_wql[E_DIM * E_DIM];
__device__ float g_Y [ROWS * 2 * E_DIM];
__device__ float g_q [ROWS * E_DIM];
__device__ float g_k [ROWS * E_DIM];
__device__ float g_v [ROWS * E_DIM];
__device__ float g_wp[ROWS * 2 * H_NUM];
__device__ bf16  g_ah[ROWS * E_DIM];
__device__ bf16  g_al[ROWS * E_DIM];

// ---------------- helpers ---------------------------------------------------
__device__ __forceinline__ float siluf(float x)    { return x / (1.0f + expf(-x)); }
__device__ __forceinline__ float silu_fast(float x){ return x / (1.0f + __expf(-x)); }
__device__ __forceinline__ float sigmoid_fast(float x){ return 1.0f / (1.0f + __expf(-x)); }

// fp32 -> (hi, lo) bf16 split
__global__ void split_kernel(const float* __restrict__ src,
                             bf16* __restrict__ hi, bf16* __restrict__ lo, int n)
{
    for (int i = blockIdx.x * blockDim.x + threadIdx.x; i < n;
         i += gridDim.x * blockDim.x) {
        float v = src[i];
        bf16 h = __float2bfloat16(v);
        hi[i] = h;
        lo[i] = __float2bfloat16(v - __bfloat162float(h));
    }
}

// ---------------- bf16x3 split GEMM (mma.m16n8k16, cp.async double-buffer) --
#define BM 128
#define BN 128
#define BKC 32
#define ASTR 40    /* BKC + 8 pad (halves) */
#define BSTR 136   /* BN  + 8 pad (halves) */
#define A_ST (BM * ASTR)   /* 5120 halves per stage */
#define B_ST (BKC * BSTR)  /* 4352 halves per stage */
#define GEMM_SMEM ((4 * A_ST + 4 * B_ST) * 2)  /* bytes: 75776 */

__device__ __forceinline__ void cp16(bf16* dst, const bf16* src)
{
    uint32_t d = (uint32_t)__cvta_generic_to_shared(dst);
    asm volatile("cp.async.cg.shared.global [%0], [%1], 16;\n" :: "r"(d), "l"(src));
}
__device__ __forceinline__ void cp_commit(){ asm volatile("cp.async.commit_group;\n"); }
__device__ __forceinline__ void cp_wait0() { asm volatile("cp.async.wait_group 0;\n"); }

__device__ __forceinline__ void ldsm4(uint32_t &r0, uint32_t &r1, uint32_t &r2, uint32_t &r3,
                                      const bf16* p)
{
    uint32_t a = (uint32_t)__cvta_generic_to_shared(p);
    asm volatile("ldmatrix.sync.aligned.m8n8.x4.shared.b16 {%0,%1,%2,%3}, [%4];\n"
                 : "=r"(r0), "=r"(r1), "=r"(r2), "=r"(r3) : "r"(a));
}
__device__ __forceinline__ void ldsm4t(uint32_t &r0, uint32_t &r1, uint32_t &r2, uint32_t &r3,
                                       const bf16* p)
{
    uint32_t a = (uint32_t)__cvta_generic_to_shared(p);
    asm volatile("ldmatrix.sync.aligned.m8n8.x4.trans.shared.b16 {%0,%1,%2,%3}, [%4];\n"
                 : "=r"(r0), "=r"(r1), "=r"(r2), "=r"(r3) : "r"(a));
}
__device__ __forceinline__ void mma_bf16(float* c, const uint32_t* a, const uint32_t* b)
{
    asm volatile("mma.sync.aligned.m16n8k16.row.col.f32.bf16.bf16.f32 "
                 "{%0,%1,%2,%3}, {%4,%5,%6,%7}, {%8,%9}, {%0,%1,%2,%3};\n"
                 : "+f"(c[0]), "+f"(c[1]), "+f"(c[2]), "+f"(c[3])
                 : "r"(a[0]), "r"(a[1]), "r"(a[2]), "r"(a[3]), "r"(b[0]), "r"(b[1]));
}

// C = (Ah+Al) @ (Bh+Bl), fp32 out; EPI==1 applies silu.
template<int EPI>
__global__ __launch_bounds__(256, 1)
void gemm_split(const bf16* __restrict__ Ah, const bf16* __restrict__ Al,
                const bf16* __restrict__ Bh, const bf16* __restrict__ Bl,
                float* __restrict__ C, int M, int N, int K)
{
    extern __shared__ bf16 sm[];
    bf16* sAh = sm;
    bf16* sAl = sm + 2 * A_ST;
    bf16* sBh = sm + 4 * A_ST;
    bf16* sBl = sm + 4 * A_ST + 2 * B_ST;

    const int m0  = blockIdx.y * BM;
    const int n0  = blockIdx.x * BN;
    const int tid = threadIdx.x;

    auto load_stage = [&](int s, int kk) {
        #pragma unroll
        for (int i = 0; i < 2; i++) {
            int c  = tid + i * 256;          // 0..511
            int r  = c >> 2;
            int kc = (c & 3) * 8;
            size_t go = (size_t)(m0 + r) * K + kk + kc;
            cp16(sAh + s * A_ST + r * ASTR + kc, Ah + go);
            cp16(sAl + s * A_ST + r * ASTR + kc, Al + go);
        }
        #pragma unroll
        for (int i = 0; i < 2; i++) {
            int c  = tid + i * 256;          // 0..511
            int r  = c >> 4;
            int nc = (c & 15) * 8;
            size_t go = (size_t)(kk + r) * N + n0 + nc;
            cp16(sBh + s * B_ST + r * BSTR + nc, Bh + go);
            cp16(sBl + s * B_ST + r * BSTR + nc, Bl + go);
        }
    };

    float acc[2][8][4];
    #pragma unroll
    for (int i = 0; i < 2; i++)
        #pragma unroll
        for (int j = 0; j < 8; j++)
            #pragma unroll
            for (int c = 0; c < 4; c++) acc[i][j][c] = 0.0f;

    const int warp = tid >> 5;
    const int lane = tid & 31;
    const int wm   = warp & 3;   // 32 rows each
    const int wn   = warp >> 2;  // 64 cols each
    const int lr   = lane & 7;
    const int lsel = (lane >> 3) & 1;
    const int lhi  = lane >> 4;

    load_stage(0, 0);
    cp_commit();
    cp_wait0();
    __syncthreads();

    const int KT = K / BKC;
    for (int kt = 0; kt < KT; kt++) {
        const int cur = kt & 1;
        if (kt + 1 < KT) load_stage(cur ^ 1, (kt + 1) * BKC);
        cp_commit();

        #pragma unroll
        for (int ks = 0; ks < 2; ks++) {
            uint32_t ahf[2][4], alf[2][4], bhf[4][4], blf[4][4];
            #pragma unroll
            for (int fm = 0; fm < 2; fm++) {
                int row = wm * 32 + fm * 16 + lr + lsel * 8;
                int col = ks * 16 + lhi * 8;
                ldsm4(ahf[fm][0], ahf[fm][1], ahf[fm][2], ahf[fm][3],
                      sAh + cur * A_ST + row * ASTR + col);
                ldsm4(alf[fm][0], alf[fm][1], alf[fm][2], alf[fm][3],
                      sAl + cur * A_ST + row * ASTR + col);
            }
            #pragma unroll
            for (int g2 = 0; g2 < 4; g2++) {
                int row = ks * 16 + lr + lsel * 8;
                int col = wn * 64 + g2 * 16 + lhi * 8;
                ldsm4t(bhf[g2][0], bhf[g2][1], bhf[g2][2], bhf[g2][3],
                       sBh + cur * B_ST + row * BSTR + col);
                ldsm4t(blf[g2][0], blf[g2][1], blf[g2][2], blf[g2][3],
                       sBl + cur * B_ST + row * BSTR + col);
            }
            // Term-outermost ordering: consecutive MMAs hit 16 distinct
            // accumulators, so same-acc RAW reuse distance is 16 issues —
            // hides HMMA accumulate latency (was a 3-deep RAW chain before).
            #pragma unroll
            for (int term = 0; term < 3; term++)
                #pragma unroll
                for (int fm = 0; fm < 2; fm++)
                    #pragma unroll
                    for (int g2 = 0; g2 < 4; g2++)
                        #pragma unroll
                        for (int hf = 0; hf < 2; hf++) {
                            const int fn = g2 * 2 + hf;
                            const uint32_t* aa = (term == 2) ? alf[fm] : ahf[fm];
                            const uint32_t* bb = (term == 1) ? &blf[g2][hf * 2]
                                                             : &bhf[g2][hf * 2];
                            mma_bf16(acc[fm][fn], aa, bb);
                        }
        }
        cp_wait0();
        __syncthreads();
    }

    const int gq = lane >> 2;
    const int tq = lane & 3;
    #pragma unroll
    for (int fm = 0; fm < 2; fm++)
        #pragma unroll
        for (int fn = 0; fn < 8; fn++) {
            int row = m0 + wm * 32 + fm * 16 + gq;
            int col = n0 + wn * 64 + fn * 8 + tq * 2;
            float v0 = acc[fm][fn][0], v1 = acc[fm][fn][1];
            float v2 = acc[fm][fn][2], v3 = acc[fm][fn][3];
            if (EPI == 1) {
                v0 = silu_fast(v0); v1 = silu_fast(v1);
                v2 = silu_fast(v2); v3 = silu_fast(v3);
            }
            float* p0 = C + (size_t)row * N + col;
            p0[0] = v0; p0[1] = v1;
            float* p1 = C + (size_t)(row + 8) * N + col;
            p1[0] = v2; p1[1] = v3;
        }
}

// ---------------- silu + per-head LayerNorm (q path) ------------------------
__global__ __launch_bounds__(256)
void qln_kernel(const float* __restrict__ Y, const float* __restrict__ gg,
                const float* __restrict__ bb, float* __restrict__ q)
{
    int grp  = blockIdx.x * 8 + (threadIdx.x >> 5);
    int lane = threadIdx.x & 31;
    int row  = grp >> 4;
    int head = grp & 15;
    const float* src = Y + (size_t)row * 1024 + head * 64;
    float s0 = silu_fast(src[lane]);
    float s1 = silu_fast(src[lane + 32]);
    float sum = s0 + s1, sq = s0 * s0 + s1 * s1;
    #pragma unroll
    for (int o = 16; o > 0; o >>= 1) {
        sum += __shfl_xor_sync(0xffffffffu, sum, o);
        sq  += __shfl_xor_sync(0xffffffffu, sq,  o);
    }
    float mean = sum * (1.0f / 64.0f);
    float var  = sq * (1.0f / 64.0f) - mean * mean;
    float inv  = rsqrtf(var + 1e-5f);
    float* dst = q + (size_t)row * 1024 + head * 64;
    dst[lane]      = (s0 - mean) * inv * gg[lane]      + bb[lane];
    dst[lane + 32] = (s1 - mean) * inv * gg[lane + 32] + bb[lane + 32];
}

// ---------------- silu + LN for k, silu for v (kv path) ---------------------
__global__ __launch_bounds__(256)
void kvln_kernel(const float* __restrict__ Y, const float* __restrict__ gg,
                 const float* __restrict__ bb, float* __restrict__ k,
                 float* __restrict__ v)
{
    int grp  = blockIdx.x * 8 + (threadIdx.x >> 5);
    int lane = threadIdx.x & 31;
    int row  = grp >> 4;
    int head = grp & 15;
    const float* srck = Y + (size_t)row * 2048 + head * 64;
    float s0 = silu_fast(srck[lane]);
    float s1 = silu_fast(srck[lane + 32]);
    float sum = s0 + s1, sq = s0 * s0 + s1 * s1;
    #pragma unroll
    for (int o = 16; o > 0; o >>= 1) {
        sum += __shfl_xor_sync(0xffffffffu, sum, o);
        sq  += __shfl_xor_sync(0xffffffffu, sq,  o);
    }
    float mean = sum * (1.0f / 64.0f);
    float var  = sq * (1.0f / 64.0f) - mean * mean;
    float inv  = rsqrtf(var + 1e-5f);
    float* dk = k + (size_t)row * 1024 + head * 64;
    dk[lane]      = (s0 - mean) * inv * gg[lane]      + bb[lane];
    dk[lane + 32] = (s1 - mean) * inv * gg[lane + 32] + bb[lane + 32];
    const float* srcv = Y + (size_t)row * 2048 + 1024 + head * 64;
    float* dv = v + (size_t)row * 1024 + head * 64;
    dv[lane]      = silu_fast(srcv[lane]);
    dv[lane + 32] = silu_fast(srcv[lane + 32]);
}

// ---------------- window-param projection: wp = silu(x @ Wwin + bwin) -------
__global__ __launch_bounds__(256)
void win_kernel(const float* __restrict__ x, const float* __restrict__ Wwin,
                const float* __restrict__ bwin, float* __restrict__ wp)
{
    __shared__ float Ws[64][32];
    __shared__ float xs[8][65];
    int row0 = blockIdx.x * 8;
    int tid  = threadIdx.x;
    int r = tid >> 5, c = tid & 31;
    float acc = 0.0f;
    for (int kc = 0; kc < 1024; kc += 64) {
        #pragma unroll
        for (int i = 0; i < 8; i++) {
            int idx = tid + i * 256;
            Ws[idx >> 5][idx & 31] = Wwin[(size_t)(kc + (idx >> 5)) * 32 + (idx & 31)];
        }
        #pragma unroll
        for (int i = 0; i < 2; i++) {
            int idx = tid + i * 256;
            xs[idx >> 6][idx & 63] = x[(size_t)(row0 + (idx >> 6)) * 1024 + kc + (idx & 63)];
        }
        __syncthreads();
        #pragma unroll
        for (int kk = 0; kk < 64; kk++) acc += xs[r][kk] * Ws[kk][c];
        __syncthreads();
    }
    wp[(size_t)(row0 + r) * 32 + c] = siluf(acc + bwin[c]);
}

// ---------------- soft-windowed local attention (fp32, tiled) ---------------
#define ATT_SMEM ((128 * 65 + 144 * 65 + 144 * 65) * 4)

__global__ __launch_bounds__(128)
void attn_kernel(const float* __restrict__ q, const float* __restrict__ k,
                 const float* __restrict__ v, const float* __restrict__ wp,
                 bf16* __restrict__ oh, bf16* __restrict__ ol)
{
    extern __shared__ float smf[];
    float* q_s = smf;
    float* k_s = smf + 128 * 65;
    float* v_s = smf + 128 * 65 + 144 * 65;

    const int l0 = blockIdx.x * 128;
    const int h  = blockIdx.y;
    const int b  = blockIdx.z;
    const int t  = threadIdx.x;
    const size_t bl0 = (size_t)b * 2048 + l0;

    for (int idx = t; idx < 128 * 64; idx += 128) {
        int r = idx >> 6, d = idx & 63;
        q_s[r * 65 + d] = q[(bl0 + r) * 1024 + h * 64 + d];
    }
    for (int idx = t; idx < 144 * 64; idx += 128) {
        int r = idx >> 6, d = idx & 63;
        int lr2 = l0 - 8 + r;
        float kv = 0.0f, vv = 0.0f;
        if (lr2 >= 0 && lr2 < 2048) {
            size_t off = ((size_t)b * 2048 + lr2) * 1024 + h * 64 + d;
            kv = k[off]; vv = v[off];
        }
        k_s[r * 65 + d] = kv;
        v_s[r * 65 + d] = vv;
    }
    __syncthreads();

    float sc[KW];
    #pragma unroll
    for (int w = 0; w < KW; w++) sc[w] = 0.0f;
    #pragma unroll 8
    for (int d = 0; d < 64; d++) {
        float qd = q_s[t * 65 + d];
        #pragma unroll
        for (int w = 0; w < KW; w++) sc[w] += qd * k_s[(t + w) * 65 + d];
    }

    const size_t blrow = bl0 + t;
    float width = sigmoid_fast(wp[blrow * 32 + h])      * 8.0f + 0.5f;
    float sharp = sigmoid_fast(wp[blrow * 32 + 16 + h]) * 9.5f + 0.5f;

    float mx = -1e30f;
    #pragma unroll
    for (int w = 0; w < KW; w++) {
        float rel = fabsf((float)w - 8.0f);
        float smk = sigmoid_fast((width - rel) * sharp);
        sc[w] = sc[w] * 0.125f - (1.0f - smk) * 10000.0f;
        mx = fmaxf(mx, sc[w]);
    }
    float sum = 0.0f;
    #pragma unroll
    for (int w = 0; w < KW; w++) { sc[w] = __expf(sc[w] - mx); sum += sc[w]; }
    float inv = 1.0f / sum;
    #pragma unroll
    for (int w = 0; w < KW; w++) sc[w] *= inv;

    #pragma unroll 4
    for (int d = 0; d < 64; d++) {
        float o = 0.0f;
        #pragma unroll
        for (int w = 0; w < KW; w++) o += sc[w] * v_s[(t + w) * 65 + d];
        size_t off = blrow * 1024 + h * 64 + d;
        bf16 hv = __float2bfloat16(o);
        oh[off] = hv;
        ol[off] = __float2bfloat16(o - __bfloat162float(hv));
    }
}

// ---------------- launch ----------------------------------------------------
extern "C" void kernel_launch(void* const* d_in, const int* in_sizes, int n_in,
                              void* d_out, int out_size)
{
    const float* x    = (const float*)d_in[0];
    const float* Wq   = (const float*)d_in[1];
    const float* Wkv  = (const float*)d_in[2];
    const float* qg   = (const float*)d_in[3];
    const float* qb   = (const float*)d_in[4];
    const float* kg   = (const float*)d_in[5];
    const float* kb   = (const float*)d_in[6];
    const float* Wwin = (const float*)d_in[7];
    const float* bwin = (const float*)d_in[8];
    const float* Wout = (const float*)d_in[9];
    float* out = (float*)d_out;

    bf16 *xh, *xl, *wh, *wl, *wqh, *wql, *ah, *al;
    float *Y, *q, *k, *v, *wp;
    cudaGetSymbolAddress((void**)&xh,  g_xh);
    cudaGetSymbolAddress((void**)&xl,  g_xl);
    cudaGetSymbolAddress((void**)&wh,  g_wh);
    cudaGetSymbolAddress((void**)&wl,  g_wl);
    cudaGetSymbolAddress((void**)&wqh, g_wqh);
    cudaGetSymbolAddress((void**)&wql, g_wql);
    cudaGetSymbolAddress((void**)&ah,  g_ah);
    cudaGetSymbolAddress((void**)&al,  g_al);
    cudaGetSymbolAddress((void**)&Y,   g_Y);
    cudaGetSymbolAddress((void**)&q,   g_q);
    cudaGetSymbolAddress((void**)&k,   g_k);
    cudaGetSymbolAddress((void**)&v,   g_v);
    cudaGetSymbolAddress((void**)&wp,  g_wp);

    cudaFuncSetAttribute(gemm_split<0>, cudaFuncAttributeMaxDynamicSharedMemorySize, GEMM_SMEM);
    cudaFuncSetAttribute(gemm_split<1>, cudaFuncAttributeMaxDynamicSharedMemorySize, GEMM_SMEM);
    cudaFuncSetAttribute(attn_kernel,   cudaFuncAttributeMaxDynamicSharedMemorySize, ATT_SMEM);

    // splits first (Wq gets its own buffers so gemm Wq can be launch #4
    // for ncu's capture window)
    split_kernel<<<512, 256>>>(x, xh, xl, ROWS * E_DIM);
    split_kernel<<<256, 256>>>(Wq, wqh, wql, E_DIM * E_DIM);
    split_kernel<<<512, 256>>>(Wkv, wh, wl, E_DIM * 2 * E_DIM);
    // Y = x @ Wq
    gemm_split<0><<<dim3(8, 64), 256, GEMM_SMEM>>>(xh, xl, wqh, wql, Y, ROWS, E_DIM, E_DIM);
    // q = LN(silu(Y)) per head
    qln_kernel<<<16384, 256>>>(Y, qg, qb, q);
    // Y = x @ Wkv
    gemm_split<0><<<dim3(16, 64), 256, GEMM_SMEM>>>(xh, xl, wh, wl, Y, ROWS, 2 * E_DIM, E_DIM);
    // k = LN(silu(Y[:, :E])), v = silu(Y[:, E:])
    kvln_kernel<<<16384, 256>>>(Y, kg, kb, k, v);
    // wp = silu(x @ Wwin + bwin)
    win_kernel<<<1024, 256>>>(x, Wwin, bwin, wp);
    // local windowed attention -> (ah, al) split bf16
    attn_kernel<<<dim3(16, 16, 4), 128, ATT_SMEM>>>(q, k, v, wp, ah, al);
    // out = silu(attn @ Wout)  (reuse wq buffers; stream-ordered after gemm Wq)
    split_kernel<<<256, 256>>>(Wout, wqh, wql, E_DIM * E_DIM);
    gemm_split<1><<<dim3(8, 64), 256, GEMM_SMEM>>>(ah, al, wqh, wql, out, ROWS, E_DIM, E_DIM);
}

// round 17
// speedup vs baseline: 1.0382x; 1.0382x over previous
#include <cuda_runtime.h>
#include <cuda_bf16.h>
#include <cstdint>
#include <cstdio>

typedef __nv_bfloat16 bf16;

#define E_DIM 1024
#define H_NUM 16
#define D_DIM 64
#define L_SEQ 2048
#define B_NUM 4
#define ROWS 8192   /* B*L */
#define KW 17

// ---------------- scratch (static device allocations; no cudaMalloc) -------
__device__ bf16  g_xh[ROWS * E_DIM];
__device__ bf16  g_xl[ROWS * E_DIM];
__device__ bf16  g_wh[E_DIM * 2 * E_DIM];   /* Wkv split */
__device__ bf16  g_wl[E_DIM * 2 * E_DIM];
__device__ bf16  g_wqh[E_DIM * E_DIM];      /* Wq split; reused for Wout */
__device__ bf16  g_wql[E_DIM * E_DIM];
__device__ float g_Y [ROWS * 2 * E_DIM];
__device__ float g_q [ROWS * E_DIM];
__device__ float g_k [ROWS * E_DIM];
__device__ float g_v [ROWS * E_DIM];
__device__ float g_wp[ROWS * 2 * H_NUM];
__device__ bf16  g_ah[ROWS * E_DIM];
__device__ bf16  g_al[ROWS * E_DIM];

// ---------------- helpers ---------------------------------------------------
__device__ __forceinline__ float siluf(float x)    { return x / (1.0f + expf(-x)); }
__device__ __forceinline__ float silu_fast(float x){ return x / (1.0f + __expf(-x)); }
__device__ __forceinline__ float sigmoid_fast(float x){ return 1.0f / (1.0f + __expf(-x)); }

// fp32 -> (hi, lo) bf16 split
__global__ void split_kernel(const float* __restrict__ src,
                             bf16* __restrict__ hi, bf16* __restrict__ lo, int n)
{
    for (int i = blockIdx.x * blockDim.x + threadIdx.x; i < n;
         i += gridDim.x * blockDim.x) {
        float v = src[i];
        bf16 h = __float2bfloat16(v);
        hi[i] = h;
        lo[i] = __float2bfloat16(v - __bfloat162float(h));
    }
}

// ---------------- bf16x3 split GEMM (mma.m16n8k16, cp.async double-buffer) --
// 512 threads / 16 warps, warp tile 32x32: 4 warps per SMSP for latency hiding
// (R14 ncu: occ=12.5%, issue=15.7%, tensor=46.5% with only 2 warps/SMSP).
#define BM 128
#define BN 128
#define BKC 32
#define ASTR 40    /* BKC + 8 pad (halves) */
#define BSTR 136   /* BN  + 8 pad (halves) */
#define A_ST (BM * ASTR)   /* 5120 halves per stage */
#define B_ST (BKC * BSTR)  /* 4352 halves per stage */
#define GEMM_SMEM ((4 * A_ST + 4 * B_ST) * 2)  /* bytes: 75776 */

__device__ __forceinline__ void cp16(bf16* dst, const bf16* src)
{
    uint32_t d = (uint32_t)__cvta_generic_to_shared(dst);
    asm volatile("cp.async.cg.shared.global [%0], [%1], 16;\n" :: "r"(d), "l"(src));
}
__device__ __forceinline__ void cp_commit(){ asm volatile("cp.async.commit_group;\n"); }
__device__ __forceinline__ void cp_wait0() { asm volatile("cp.async.wait_group 0;\n"); }

__device__ __forceinline__ void ldsm4(uint32_t &r0, uint32_t &r1, uint32_t &r2, uint32_t &r3,
                                      const bf16* p)
{
    uint32_t a = (uint32_t)__cvta_generic_to_shared(p);
    asm volatile("ldmatrix.sync.aligned.m8n8.x4.shared.b16 {%0,%1,%2,%3}, [%4];\n"
                 : "=r"(r0), "=r"(r1), "=r"(r2), "=r"(r3) : "r"(a));
}
__device__ __forceinline__ void ldsm4t(uint32_t &r0, uint32_t &r1, uint32_t &r2, uint32_t &r3,
                                       const bf16* p)
{
    uint32_t a = (uint32_t)__cvta_generic_to_shared(p);
    asm volatile("ldmatrix.sync.aligned.m8n8.x4.trans.shared.b16 {%0,%1,%2,%3}, [%4];\n"
                 : "=r"(r0), "=r"(r1), "=r"(r2), "=r"(r3) : "r"(a));
}
__device__ __forceinline__ void mma_bf16(float* c, const uint32_t* a, const uint32_t* b)
{
    asm volatile("mma.sync.aligned.m16n8k16.row.col.f32.bf16.bf16.f32 "
                 "{%0,%1,%2,%3}, {%4,%5,%6,%7}, {%8,%9}, {%0,%1,%2,%3};\n"
                 : "+f"(c[0]), "+f"(c[1]), "+f"(c[2]), "+f"(c[3])
                 : "r"(a[0]), "r"(a[1]), "r"(a[2]), "r"(a[3]), "r"(b[0]), "r"(b[1]));
}

// C = (Ah+Al) @ (Bh+Bl), fp32 out; EPI==1 applies silu.
template<int EPI>
__global__ __launch_bounds__(512, 1)
void gemm_split(const bf16* __restrict__ Ah, const bf16* __restrict__ Al,
                const bf16* __restrict__ Bh, const bf16* __restrict__ Bl,
                float* __restrict__ C, int M, int N, int K)
{
    extern __shared__ bf16 sm[];
    bf16* sAh = sm;
    bf16* sAl = sm + 2 * A_ST;
    bf16* sBh = sm + 4 * A_ST;
    bf16* sBl = sm + 4 * A_ST + 2 * B_ST;

    const int m0  = blockIdx.y * BM;
    const int n0  = blockIdx.x * BN;
    const int tid = threadIdx.x;

    auto load_stage = [&](int s, int kk) {
        {
            int r  = tid >> 2;          // 0..127
            int kc = (tid & 3) * 8;
            size_t go = (size_t)(m0 + r) * K + kk + kc;
            cp16(sAh + s * A_ST + r * ASTR + kc, Ah + go);
            cp16(sAl + s * A_ST + r * ASTR + kc, Al + go);
        }
        {
            int r  = tid >> 4;          // 0..31
            int nc = (tid & 15) * 8;
            size_t go = (size_t)(kk + r) * N + n0 + nc;
            cp16(sBh + s * B_ST + r * BSTR + nc, Bh + go);
            cp16(sBl + s * B_ST + r * BSTR + nc, Bl + go);
        }
    };

    float acc[2][4][4];
    #pragma unroll
    for (int i = 0; i < 2; i++)
        #pragma unroll
        for (int j = 0; j < 4; j++)
            #pragma unroll
            for (int c = 0; c < 4; c++) acc[i][j][c] = 0.0f;

    const int warp = tid >> 5;   // 0..15
    const int lane = tid & 31;
    const int wm   = warp & 3;   // 4 row-groups of 32
    const int wn   = warp >> 2;  // 4 col-groups of 32
    const int lr   = lane & 7;
    const int lsel = (lane >> 3) & 1;
    const int lhi  = lane >> 4;

    load_stage(0, 0);
    cp_commit();
    cp_wait0();
    __syncthreads();

    const int KT = K / BKC;
    for (int kt = 0; kt < KT; kt++) {
        const int cur = kt & 1;
        if (kt + 1 < KT) load_stage(cur ^ 1, (kt + 1) * BKC);
        cp_commit();

        #pragma unroll
        for (int ks = 0; ks < 2; ks++) {
            uint32_t ahf[2][4], alf[2][4], bhf[2][4], blf[2][4];
            #pragma unroll
            for (int fm = 0; fm < 2; fm++) {
                int row = wm * 32 + fm * 16 + lr + lsel * 8;
                int col = ks * 16 + lhi * 8;
                ldsm4(ahf[fm][0], ahf[fm][1], ahf[fm][2], ahf[fm][3],
                      sAh + cur * A_ST + row * ASTR + col);
                ldsm4(alf[fm][0], alf[fm][1], alf[fm][2], alf[fm][3],
                      sAl + cur * A_ST + row * ASTR + col);
            }
            #pragma unroll
            for (int g2 = 0; g2 < 2; g2++) {
                int row = ks * 16 + lr + lsel * 8;
                int col = wn * 32 + g2 * 16 + lhi * 8;
                ldsm4t(bhf[g2][0], bhf[g2][1], bhf[g2][2], bhf[g2][3],
                       sBh + cur * B_ST + row * BSTR + col);
                ldsm4t(blf[g2][0], blf[g2][1], blf[g2][2], blf[g2][3],
                       sBl + cur * B_ST + row * BSTR + col);
            }
            #pragma unroll
            for (int term = 0; term < 3; term++)
                #pragma unroll
                for (int fm = 0; fm < 2; fm++)
                    #pragma unroll
                    for (int g2 = 0; g2 < 2; g2++)
                        #pragma unroll
                        for (int hf = 0; hf < 2; hf++) {
                            const int fn = g2 * 2 + hf;
                            const uint32_t* aa = (term == 2) ? alf[fm] : ahf[fm];
                            const uint32_t* bb = (term == 1) ? &blf[g2][hf * 2]
                                                             : &bhf[g2][hf * 2];
                            mma_bf16(acc[fm][fn], aa, bb);
                        }
        }
        cp_wait0();
        __syncthreads();
    }

    const int gq = lane >> 2;
    const int tq = lane & 3;
    #pragma unroll
    for (int fm = 0; fm < 2; fm++)
        #pragma unroll
        for (int fn = 0; fn < 4; fn++) {
            int row = m0 + wm * 32 + fm * 16 + gq;
            int col = n0 + wn * 32 + fn * 8 + tq * 2;
            float v0 = acc[fm][fn][0], v1 = acc[fm][fn][1];
            float v2 = acc[fm][fn][2], v3 = acc[fm][fn][3];
            if (EPI == 1) {
                v0 = silu_fast(v0); v1 = silu_fast(v1);
                v2 = silu_fast(v2); v3 = silu_fast(v3);
            }
            float* p0 = C + (size_t)row * N + col;
            p0[0] = v0; p0[1] = v1;
            float* p1 = C + (size_t)(row + 8) * N + col;
            p1[0] = v2; p1[1] = v3;
        }
}

// ---------------- silu + per-head LayerNorm (q path) ------------------------
__global__ __launch_bounds__(256)
void qln_kernel(const float* __restrict__ Y, const float* __restrict__ gg,
                const float* __restrict__ bb, float* __restrict__ q)
{
    int grp  = blockIdx.x * 8 + (threadIdx.x >> 5);
    int lane = threadIdx.x & 31;
    int row  = grp >> 4;
    int head = grp & 15;
    const float* src = Y + (size_t)row * 1024 + head * 64;
    float s0 = silu_fast(src[lane]);
    float s1 = silu_fast(src[lane + 32]);
    float sum = s0 + s1, sq = s0 * s0 + s1 * s1;
    #pragma unroll
    for (int o = 16; o > 0; o >>= 1) {
        sum += __shfl_xor_sync(0xffffffffu, sum, o);
        sq  += __shfl_xor_sync(0xffffffffu, sq,  o);
    }
    float mean = sum * (1.0f / 64.0f);
    float var  = sq * (1.0f / 64.0f) - mean * mean;
    float inv  = rsqrtf(var + 1e-5f);
    float* dst = q + (size_t)row * 1024 + head * 64;
    dst[lane]      = (s0 - mean) * inv * gg[lane]      + bb[lane];
    dst[lane + 32] = (s1 - mean) * inv * gg[lane + 32] + bb[lane + 32];
}

// ---------------- silu + LN for k, silu for v (kv path) ---------------------
__global__ __launch_bounds__(256)
void kvln_kernel(const float* __restrict__ Y, const float* __restrict__ gg,
                 const float* __restrict__ bb, float* __restrict__ k,
                 float* __restrict__ v)
{
    int grp  = blockIdx.x * 8 + (threadIdx.x >> 5);
    int lane = threadIdx.x & 31;
    int row  = grp >> 4;
    int head = grp & 15;
    const float* srck = Y + (size_t)row * 2048 + head * 64;
    float s0 = silu_fast(srck[lane]);
    float s1 = silu_fast(srck[lane + 32]);
    float sum = s0 + s1, sq = s0 * s0 + s1 * s1;
    #pragma unroll
    for (int o = 16; o > 0; o >>= 1) {
        sum += __shfl_xor_sync(0xffffffffu, sum, o);
        sq  += __shfl_xor_sync(0xffffffffu, sq,  o);
    }
    float mean = sum * (1.0f / 64.0f);
    float var  = sq * (1.0f / 64.0f) - mean * mean;
    float inv  = rsqrtf(var + 1e-5f);
    float* dk = k + (size_t)row * 1024 + head * 64;
    dk[lane]      = (s0 - mean) * inv * gg[lane]      + bb[lane];
    dk[lane + 32] = (s1 - mean) * inv * gg[lane + 32] + bb[lane + 32];
    const float* srcv = Y + (size_t)row * 2048 + 1024 + head * 64;
    float* dv = v + (size_t)row * 1024 + head * 64;
    dv[lane]      = silu_fast(srcv[lane]);
    dv[lane + 32] = silu_fast(srcv[lane + 32]);
}

// ---------------- window-param projection: wp = silu(x @ Wwin + bwin) -------
__global__ __launch_bounds__(256)
void win_kernel(const float* __restrict__ x, const float* __restrict__ Wwin,
                const float* __restrict__ bwin, float* __restrict__ wp)
{
    __shared__ float Ws[64][32];
    __shared__ float xs[8][65];
    int row0 = blockIdx.x * 8;
    int tid  = threadIdx.x;
    int r = tid >> 5, c = tid & 31;
    float acc = 0.0f;
    for (int kc = 0; kc < 1024; kc += 64) {
        #pragma unroll
        for (int i = 0; i < 8; i++) {
            int idx = tid + i * 256;
            Ws[idx >> 5][idx & 31] = Wwin[(size_t)(kc + (idx >> 5)) * 32 + (idx & 31)];
        }
        #pragma unroll
        for (int i = 0; i < 2; i++) {
            int idx = tid + i * 256;
            xs[idx >> 6][idx & 63] = x[(size_t)(row0 + (idx >> 6)) * 1024 + kc + (idx & 63)];
        }
        __syncthreads();
        #pragma unroll
        for (int kk = 0; kk < 64; kk++) acc += xs[r][kk] * Ws[kk][c];
        __syncthreads();
    }
    wp[(size_t)(row0 + r) * 32 + c] = siluf(acc + bwin[c]);
}

// ---------------- soft-windowed local attention (fp32, tiled) ---------------
#define ATT_SMEM ((128 * 65 + 144 * 65 + 144 * 65) * 4)

__global__ __launch_bounds__(128)
void attn_kernel(const float* __restrict__ q, const float* __restrict__ k,
                 const float* __restrict__ v, const float* __restrict__ wp,
                 bf16* __restrict__ oh, bf16* __restrict__ ol)
{
    extern __shared__ float smf[];
    float* q_s = smf;
    float* k_s = smf + 128 * 65;
    float* v_s = smf + 128 * 65 + 144 * 65;

    const int l0 = blockIdx.x * 128;
    const int h  = blockIdx.y;
    const int b  = blockIdx.z;
    const int t  = threadIdx.x;
    const size_t bl0 = (size_t)b * 2048 + l0;

    for (int idx = t; idx < 128 * 64; idx += 128) {
        int r = idx >> 6, d = idx & 63;
        q_s[r * 65 + d] = q[(bl0 + r) * 1024 + h * 64 + d];
    }
    for (int idx = t; idx < 144 * 64; idx += 128) {
        int r = idx >> 6, d = idx & 63;
        int lr2 = l0 - 8 + r;
        float kv = 0.0f, vv = 0.0f;
        if (lr2 >= 0 && lr2 < 2048) {
            size_t off = ((size_t)b * 2048 + lr2) * 1024 + h * 64 + d;
            kv = k[off]; vv = v[off];
        }
        k_s[r * 65 + d] = kv;
        v_s[r * 65 + d] = vv;
    }
    __syncthreads();

    float sc[KW];
    #pragma unroll
    for (int w = 0; w < KW; w++) sc[w] = 0.0f;
    #pragma unroll 8
    for (int d = 0; d < 64; d++) {
        float qd = q_s[t * 65 + d];
        #pragma unroll
        for (int w = 0; w < KW; w++) sc[w] += qd * k_s[(t + w) * 65 + d];
    }

    const size_t blrow = bl0 + t;
    float width = sigmoid_fast(wp[blrow * 32 + h])      * 8.0f + 0.5f;
    float sharp = sigmoid_fast(wp[blrow * 32 + 16 + h]) * 9.5f + 0.5f;

    float mx = -1e30f;
    #pragma unroll
    for (int w = 0; w < KW; w++) {
        float rel = fabsf((float)w - 8.0f);
        float smk = sigmoid_fast((width - rel) * sharp);
        sc[w] = sc[w] * 0.125f - (1.0f - smk) * 10000.0f;
        mx = fmaxf(mx, sc[w]);
    }
    float sum = 0.0f;
    #pragma unroll
    for (int w = 0; w < KW; w++) { sc[w] = __expf(sc[w] - mx); sum += sc[w]; }
    float inv = 1.0f / sum;
    #pragma unroll
    for (int w = 0; w < KW; w++) sc[w] *= inv;

    #pragma unroll 4
    for (int d = 0; d < 64; d++) {
        float o = 0.0f;
        #pragma unroll
        for (int w = 0; w < KW; w++) o += sc[w] * v_s[(t + w) * 65 + d];
        size_t off = blrow * 1024 + h * 64 + d;
        bf16 hv = __float2bfloat16(o);
        oh[off] = hv;
        ol[off] = __float2bfloat16(o - __bfloat162float(hv));
    }
}

// ---------------- launch ----------------------------------------------------
extern "C" void kernel_launch(void* const* d_in, const int* in_sizes, int n_in,
                              void* d_out, int out_size)
{
    const float* x    = (const float*)d_in[0];
    const float* Wq   = (const float*)d_in[1];
    const float* Wkv  = (const float*)d_in[2];
    const float* qg   = (const float*)d_in[3];
    const float* qb   = (const float*)d_in[4];
    const float* kg   = (const float*)d_in[5];
    const float* kb   = (const float*)d_in[6];
    const float* Wwin = (const float*)d_in[7];
    const float* bwin = (const float*)d_in[8];
    const float* Wout = (const float*)d_in[9];
    float* out = (float*)d_out;

    bf16 *xh, *xl, *wh, *wl, *wqh, *wql, *ah, *al;
    float *Y, *q, *k, *v, *wp;
    cudaGetSymbolAddress((void**)&xh,  g_xh);
    cudaGetSymbolAddress((void**)&xl,  g_xl);
    cudaGetSymbolAddress((void**)&wh,  g_wh);
    cudaGetSymbolAddress((void**)&wl,  g_wl);
    cudaGetSymbolAddress((void**)&wqh, g_wqh);
    cudaGetSymbolAddress((void**)&wql, g_wql);
    cudaGetSymbolAddress((void**)&ah,  g_ah);
    cudaGetSymbolAddress((void**)&al,  g_al);
    cudaGetSymbolAddress((void**)&Y,   g_Y);
    cudaGetSymbolAddress((void**)&q,   g_q);
    cudaGetSymbolAddress((void**)&k,   g_k);
    cudaGetSymbolAddress((void**)&v,   g_v);
    cudaGetSymbolAddress((void**)&wp,  g_wp);

    cudaFuncSetAttribute(gemm_split<0>, cudaFuncAttributeMaxDynamicSharedMemorySize, GEMM_SMEM);
    cudaFuncSetAttribute(gemm_split<1>, cudaFuncAttributeMaxDynamicSharedMemorySize, GEMM_SMEM);
    cudaFuncSetAttribute(attn_kernel,   cudaFuncAttributeMaxDynamicSharedMemorySize, ATT_SMEM);

    // splits first (gemm Wq stays launch #4 for the ncu capture window)
    split_kernel<<<512, 256>>>(x, xh, xl, ROWS * E_DIM);
    split_kernel<<<256, 256>>>(Wq, wqh, wql, E_DIM * E_DIM);
    split_kernel<<<512, 256>>>(Wkv, wh, wl, E_DIM * 2 * E_DIM);
    // Y = x @ Wq
    gemm_split<0><<<dim3(8, 64), 512, GEMM_SMEM>>>(xh, xl, wqh, wql, Y, ROWS, E_DIM, E_DIM);
    // q = LN(silu(Y)) per head
    qln_kernel<<<16384, 256>>>(Y, qg, qb, q);
    // Y = x @ Wkv
    gemm_split<0><<<dim3(16, 64), 512, GEMM_SMEM>>>(xh, xl, wh, wl, Y, ROWS, 2 * E_DIM, E_DIM);
    // k = LN(silu(Y[:, :E])), v = silu(Y[:, E:])
    kvln_kernel<<<16384, 256>>>(Y, kg, kb, k, v);
    // wp = silu(x @ Wwin + bwin)
    win_kernel<<<1024, 256>>>(x, Wwin, bwin, wp);
    // local windowed attention -> (ah, al) split bf16
    attn_kernel<<<dim3(16, 16, 4), 128, ATT_SMEM>>>(q, k, v, wp, ah, al);
    // out = silu(attn @ Wout)  (reuse wq buffers; stream-ordered after gemm Wq)
    split_kernel<<<256, 256>>>(Wout, wqh, wql, E_DIM * E_DIM);
    gemm_split<1><<<dim3(8, 64), 512, GEMM_SMEM>>>(ah, al, wqh, wql, out, ROWS, E_DIM, E_DIM);
}